// round 4
// baseline (speedup 1.0000x reference)
#include <cuda_runtime.h>
#include <math.h>

// Chamfer distance, B=4, N=M=8192, 3D.
// d_out (float32): dist1[B*N] | dist2[B*M] | idx1[B*N] | idx2[B*M]
//  - packed f32x2 add/mul (exact per-lane rn; NO FMA -> bit-match XLA)
//  - candidates staged NEGATED in smem; LDS.128 as ulonglong2 (no pack MOVs)
//  - branch-free hot loop: track (best, group_base) via predicated selects;
//    within-group argmin recovered ONCE in an epilogue recompute from GMEM
//  - 4 segment-threads per query -> 48 warps/SM; exact (d, idx) combine

#define QPB 128            // 32 queries x 4 segments
#define NQ_BLK 32
#define NSEG 4
#define CH 1024            // candidates staged per chunk
#define SEG 256            // candidates per segment per chunk

typedef unsigned long long u64;

__device__ __forceinline__ void unpack2(float& lo, float& hi, u64 v) {
    asm("mov.b64 {%0, %1}, %2;" : "=f"(lo), "=f"(hi) : "l"(v));
}
__device__ __forceinline__ u64 pack2(float lo, float hi) {
    u64 r;
    asm("mov.b64 %0, {%1, %2};" : "=l"(r) : "f"(lo), "f"(hi));
    return r;
}
__device__ __forceinline__ u64 add2(u64 a, u64 b) {
    u64 r;
    asm("add.rn.f32x2 %0, %1, %2;" : "=l"(r) : "l"(a), "l"(b));
    return r;
}
__device__ __forceinline__ u64 mul2(u64 a, u64 b) {
    u64 r;
    asm("mul.rn.f32x2 %0, %1, %2;" : "=l"(r) : "l"(a), "l"(b));
    return r;
}

__global__ __launch_bounds__(QPB, 12) void chamfer_kernel(
    const float* __restrict__ xyz1,
    const float* __restrict__ xyz2,
    float* __restrict__ out,
    int N, int M, int B)
{
    __shared__ __align__(16) float smem_f[3 * CH];   // negated SoA: x | y | z
    __shared__ float rbest[QPB];
    __shared__ int   rbi[QPB];

    float* sx = smem_f;
    float* sy = smem_f + CH;
    float* sz = smem_f + 2 * CH;

    const int dir = blockIdx.z;   // 0: xyz1->xyz2, 1: xyz2->xyz1
    const int b   = blockIdx.y;

    const float* q; const float* c;
    float* outd; float* outi;
    int Nq, Nc;
    if (dir == 0) {
        q = xyz1; c = xyz2; Nq = N; Nc = M;
        outd = out;
        outi = out + (size_t)B * N + (size_t)B * M;
    } else {
        q = xyz2; c = xyz1; Nq = M; Nc = N;
        outd = out + (size_t)B * N;
        outi = out + (size_t)B * N + (size_t)B * M + (size_t)B * N;
    }

    const int tid = threadIdx.x;
    const int ql  = tid & (NQ_BLK - 1);   // query lane
    const int seg = tid >> 5;             // 0..3 candidate segment
    const int qi  = blockIdx.x * NQ_BLK + ql;

    const float* qb = q + ((size_t)b * Nq + qi) * 3;
    const float* cb = c + (size_t)b * Nc * 3;

    const float px = qb[0];
    const float py = qb[1];
    const float pz = qb[2];
    const u64 pxx = pack2(px, px);
    const u64 pyy = pack2(py, py);
    const u64 pzz = pack2(pz, pz);

    // Segment views of the staged chunk (64-bit lanes, LDS.128 pairs).
    const ulonglong2* sxv = (const ulonglong2*)(sx + seg * SEG);
    const ulonglong2* syv = (const ulonglong2*)(sy + seg * SEG);
    const ulonglong2* szv = (const ulonglong2*)(sz + seg * SEG);

    float best = INFINITY;
    int   bg   = 0;      // global candidate index of winning 8-group's base

    for (int base = 0; base < Nc; base += CH) {
        __syncthreads();
        for (int t = tid; t < CH; t += QPB) {
            const float* p = cb + (size_t)(base + t) * 3;
            sx[t] = -p[0];
            sy[t] = -p[1];
            sz[t] = -p[2];
        }
        __syncthreads();

        const int segbase = base + seg * SEG;

        #pragma unroll 4
        for (int g = 0; g < SEG / 8; ++g) {
            const ulonglong2 X0 = sxv[2 * g], X1 = sxv[2 * g + 1];
            const ulonglong2 Y0 = syv[2 * g], Y1 = syv[2 * g + 1];
            const ulonglong2 Z0 = szv[2 * g], Z1 = szv[2 * g + 1];

            u64 dx01 = add2(pxx, X0.x);
            u64 dx23 = add2(pxx, X0.y);
            u64 dx45 = add2(pxx, X1.x);
            u64 dx67 = add2(pxx, X1.y);
            u64 dy01 = add2(pyy, Y0.x);
            u64 dy23 = add2(pyy, Y0.y);
            u64 dy45 = add2(pyy, Y1.x);
            u64 dy67 = add2(pyy, Y1.y);
            u64 dz01 = add2(pzz, Z0.x);
            u64 dz23 = add2(pzz, Z0.y);
            u64 dz45 = add2(pzz, Z1.x);
            u64 dz67 = add2(pzz, Z1.y);

            u64 d01 = add2(add2(mul2(dx01, dx01), mul2(dy01, dy01)), mul2(dz01, dz01));
            u64 d23 = add2(add2(mul2(dx23, dx23), mul2(dy23, dy23)), mul2(dz23, dz23));
            u64 d45 = add2(add2(mul2(dx45, dx45), mul2(dy45, dy45)), mul2(dz45, dz45));
            u64 d67 = add2(add2(mul2(dx67, dx67), mul2(dy67, dy67)), mul2(dz67, dz67));

            float d0, d1, d2, d3, d4, d5, d6, d7;
            unpack2(d0, d1, d01);
            unpack2(d2, d3, d23);
            unpack2(d4, d5, d45);
            unpack2(d6, d7, d67);

            const float m = fminf(fminf(fminf(d0, d1), fminf(d2, d3)),
                                  fminf(fminf(d4, d5), fminf(d6, d7)));

            // Branch-free: strict < keeps earliest group on ties.
            const bool imp = m < best;
            best = imp ? m : best;
            bg   = imp ? segbase + g * 8 : bg;
        }
    }

    // Epilogue: recover within-group index by recomputing the winning group
    // from GMEM with identical rn arithmetic (bit-exact vs packed loop).
    {
        const float* p = cb + (size_t)bg * 3;
        float d[8];
        #pragma unroll
        for (int k = 0; k < 8; ++k) {
            float dx = __fsub_rn(px, p[3 * k + 0]);
            float dy = __fsub_rn(py, p[3 * k + 1]);
            float dz = __fsub_rn(pz, p[3 * k + 2]);
            d[k] = __fadd_rn(__fadd_rn(__fmul_rn(dx, dx), __fmul_rn(dy, dy)),
                             __fmul_rn(dz, dz));
        }
        int s = bg + 7;   // descending scan -> lowest k with d[k]==best wins
        if (d[6] == best) s = bg + 6;
        if (d[5] == best) s = bg + 5;
        if (d[4] == best) s = bg + 4;
        if (d[3] == best) s = bg + 3;
        if (d[2] == best) s = bg + 2;
        if (d[1] == best) s = bg + 1;
        if (d[0] == best) s = bg;
        rbest[tid] = best;
        rbi[tid]   = s;
    }
    __syncthreads();

    // Combine 4 segments per query: lexicographic (d, idx) min == first occurrence.
    if (tid < NQ_BLK) {
        float bd = rbest[tid];
        int   bix = rbi[tid];
        #pragma unroll
        for (int s = 1; s < NSEG; ++s) {
            const float od = rbest[tid + s * NQ_BLK];
            const int   oi = rbi[tid + s * NQ_BLK];
            if (od < bd || (od == bd && oi < bix)) { bd = od; bix = oi; }
        }
        outd[(size_t)b * Nq + qi] = bd;
        outi[(size_t)b * Nq + qi] = (float)bix;   // <= 8191, exact in fp32
    }
}

extern "C" void kernel_launch(void* const* d_in, const int* in_sizes, int n_in,
                              void* d_out, int out_size)
{
    const float* xyz1 = (const float*)d_in[0];  // [4, 8192, 3]
    const float* xyz2 = (const float*)d_in[1];  // [4, 8192, 3]
    float* out = (float*)d_out;

    const int B = 4;
    const int N = in_sizes[0] / (B * 3);  // 8192
    const int M = in_sizes[1] / (B * 3);  // 8192

    dim3 block(QPB, 1, 1);
    dim3 grid(N / NQ_BLK, B, 2);   // 2048 blocks x 128 threads
    chamfer_kernel<<<grid, block>>>(xyz1, xyz2, out, N, M, B);
}